// round 5
// baseline (speedup 1.0000x reference)
#include <cuda_runtime.h>
#include <cuda_bf16.h>
#include <cstdint>

// SelfConnectionIntro via baseline-PTX HMMA (mma.sync m16n8k16 bf16):
// out_l[z,w,k] = alpha * sum_v opr[z,v] * (x_l[:,:,k] @ W_l[:,v,:])[z,w]
// Split-bf16 (3 terms: AhBh + AhBl + AlBh). A(x) hi/lo in smem via ldmatrix;
// B(W) pre-fragmented in global to per-lane HMMA layout (verified in R4).
// R5: warp tile m32xn32, VC=2 species per pass (two independent MMA chains),
// CTA n-tile 64 -> no register spills (R4 was at the 255-reg cap).

__device__ __forceinline__ uint32_t smem_u32(const void* p) {
    uint32_t a;
    asm("{ .reg .u64 t; cvta.to.shared.u64 t, %1; cvt.u32.u64 %0, t; }" : "=r"(a) : "l"(p));
    return a;
}
__device__ __forceinline__ void ldmat_x4(uint32_t r[4], uint32_t a) {
    asm volatile("ldmatrix.sync.aligned.m8n8.x4.shared.b16 {%0,%1,%2,%3}, [%4];"
                 : "=r"(r[0]), "=r"(r[1]), "=r"(r[2]), "=r"(r[3]) : "r"(a));
}
__device__ __forceinline__ void mma16816(float d[4], const uint32_t a[4],
                                         uint32_t b0, uint32_t b1) {
    asm volatile("mma.sync.aligned.m16n8k16.row.col.f32.bf16.bf16.f32 "
                 "{%0,%1,%2,%3},{%4,%5,%6,%7},{%8,%9},{%0,%1,%2,%3};"
                 : "+f"(d[0]), "+f"(d[1]), "+f"(d[2]), "+f"(d[3])
                 : "r"(a[0]), "r"(a[1]), "r"(a[2]), "r"(a[3]), "r"(b0), "r"(b1));
}

// Pre-fragmented B images: [h(hi/lo)][v(16)][ks][nb][lane(32)] as uint2 (b0,b1).
__device__ uint2 BIMG0[2 * 16 * 8 * 16 * 32];  // path0 U=128 N=128
__device__ uint2 BIMG1[2 * 16 * 4 *  8 * 32];  // path1 U=64  N=64
__device__ uint2 BIMG2[2 * 16 * 2 *  4 * 32];  // path2 U=32  N=32

// W layout [U][16][NTOT]. B frag (k16 x n8): lane t, reg r, half hh:
//   u = ks*16 + 2*(t&3) + hh + r*8 ; n = nb*8 + t/4 ; value = W[u][v][n].
template<int U, int NTOT>
__global__ void prepB(const float* __restrict__ W, uint2* __restrict__ dst) {
    constexpr int KS = U / 16, NBT = NTOT / 8;
    const int total = 2 * 16 * KS * NBT * 32;
    for (int i = blockIdx.x * blockDim.x + threadIdx.x; i < total;
         i += gridDim.x * blockDim.x) {
        int lane = i & 31, r1 = i >> 5;
        int nbg = r1 % NBT; r1 /= NBT;
        int ks = r1 % KS;  r1 /= KS;
        int v = r1 & 15, h = r1 >> 4;
        int n = nbg * 8 + (lane >> 2);
        uint32_t wr[2];
#pragma unroll
        for (int r = 0; r < 2; r++) {
            uint32_t word = 0;
#pragma unroll
            for (int hh = 0; hh < 2; hh++) {
                int u = ks * 16 + 2 * (lane & 3) + hh + r * 8;
                float f = W[((size_t)u * 16 + v) * NTOT + n];
                __nv_bfloat16 bh = __float2bfloat16(f);
                __nv_bfloat16 bo = h ? __float2bfloat16(f - __bfloat162float(bh)) : bh;
                uint16_t bits = *(uint16_t*)&bo;
                word |= (uint32_t)bits << (hh * 16);
            }
            wr[r] = word;
        }
        dst[i] = make_uint2(wr[0], wr[1]);
    }
}

// Main kernel. CTA = 128-node tile x NT output channels, one k-component.
// Warp grid WM x WN; warp tile (MW*16) x (NBW*8); VC species per pass.
template<int U, int NTOT, int NT, int D, int WM, int WN, int MW, int NBW, int VC>
__global__ __launch_bounds__(WM * WN * 32)
void fctp_hmma(const float* __restrict__ x, const float* __restrict__ opr,
               const uint2* __restrict__ Bimg, float* __restrict__ out,
               int Z, int xoff, float alpha)
{
    constexpr int KS = U / 16, NBT = NTOT / 8, RS = U + 8;
    constexpr int NTH = WM * WN * 32, VG = 16 / VC;
    constexpr int XB = 128 * RS * 2;
    constexpr int AR = MW * NBW * 4;

    extern __shared__ char smraw[];
    __nv_bfloat16* xh = (__nv_bfloat16*)smraw;
    __nv_bfloat16* xl = (__nv_bfloat16*)(smraw + XB);
    float* ops = (float*)(smraw + 2 * XB);                    // [128][17]

    const int tid = threadIdx.x, lane = tid & 31, wid = tid >> 5;
    const int wm = wid % WM, wn = wid / WM;
    const int moff = wm * MW * 16;
    const int nb0 = blockIdx.z * (NT / 8) + wn * NBW;         // global n8-block
    const int kc = blockIdx.y;
    const int zbase = blockIdx.x * 128;

    // Stage x (split hi/lo bf16) and opr.
    for (int e = tid; e < 128 * U; e += NTH) {
        int zl = e / U, u = e % U;
        int z = zbase + zl;
        float v = (z < Z) ? x[(size_t)z * 480 + xoff + u * D + kc] : 0.0f;
        __nv_bfloat16 h = __float2bfloat16(v);
        xh[zl * RS + u] = h;
        xl[zl * RS + u] = __float2bfloat16(v - __bfloat162float(h));
    }
    for (int e = tid; e < 128 * 16; e += NTH) {
        int zl = e >> 4, v = e & 15;
        int z = zbase + zl;
        ops[zl * 17 + v] = (z < Z) ? opr[(size_t)z * 16 + v] : 0.0f;
    }
    __syncthreads();

    const uint32_t xhB = smem_u32(xh), xlB = smem_u32(xl);
    const uint32_t aLane = (uint32_t)(moff + (lane & 15)) * (RS * 2) + ((lane >> 4) << 4);
    const uint2* pB = Bimg + (size_t)nb0 * 32 + lane;

    float acc[AR];
#pragma unroll
    for (int i = 0; i < AR; i++) acc[i] = 0.0f;

    uint32_t A[2][MW][4];
    uint2    Bf[2][VC][NBW];

    auto pfA = [&](int buf, int hsel, int ks) {
        uint32_t base = (hsel ? xlB : xhB) + aLane + ks * 32;
#pragma unroll
        for (int mb = 0; mb < MW; mb++) ldmat_x4(A[buf][mb], base + mb * 16 * RS * 2);
    };
    auto pfB = [&](int buf, int himg, int vg, int ks) {
#pragma unroll
        for (int vv = 0; vv < VC; vv++) {
            const uint2* p = pB + (size_t)((himg * 16 + vg * VC + vv) * KS + ks) * (NBT * 32);
#pragma unroll
            for (int j = 0; j < NBW; j++) Bf[buf][vv][j] = p[j * 32];
        }
    };

    pfA(0, 0, 0);
    pfB(0, 0, 0, 0);

    for (int vg = 0; vg < VG; vg++) {
        float d[VC][AR];
#pragma unroll
        for (int vv = 0; vv < VC; vv++)
#pragma unroll
            for (int i = 0; i < AR; i++) d[vv][i] = 0.0f;

#pragma unroll
        for (int t = 0; t < 3; t++) {
#pragma unroll
            for (int ks = 0; ks < KS; ks++) {
                const int s = t * KS + ks, cur = s & 1, nxt = cur ^ 1;
                int nt = t, nks = ks + 1; bool wv = false;
                if (nks == KS) { nks = 0; nt = t + 1; if (nt == 3) { nt = 0; wv = true; } }
                if (!(wv && vg == VG - 1)) {
                    int nvg = wv ? vg + 1 : vg;
                    pfA(nxt, (nt == 2) ? 1 : 0, nks);
                    pfB(nxt, (nt == 1) ? 1 : 0, nvg, nks);
                }
#pragma unroll
                for (int vv = 0; vv < VC; vv++)
#pragma unroll
                    for (int mb = 0; mb < MW; mb++)
#pragma unroll
                        for (int j = 0; j < NBW; j++)
                            mma16816(&d[vv][(mb * NBW + j) * 4], A[cur][mb],
                                     Bf[cur][vv][j].x, Bf[cur][vv][j].y);
            }
        }
        // epilogue: acc += opr[z, vg*VC+vv] * d[vv]
#pragma unroll
        for (int vv = 0; vv < VC; vv++) {
            const int v = vg * VC + vv;
#pragma unroll
            for (int mb = 0; mb < MW; mb++) {
                float o0 = ops[(moff + mb * 16 + (lane >> 2)) * 17 + v];
                float o1 = ops[(moff + mb * 16 + (lane >> 2) + 8) * 17 + v];
#pragma unroll
                for (int j = 0; j < NBW; j++) {
                    float* dd = &d[vv][(mb * NBW + j) * 4];
                    float* aa = &acc[(mb * NBW + j) * 4];
                    aa[0] = fmaf(o0, dd[0], aa[0]);
                    aa[1] = fmaf(o0, dd[1], aa[1]);
                    aa[2] = fmaf(o1, dd[2], aa[2]);
                    aa[3] = fmaf(o1, dd[3], aa[3]);
                }
            }
        }
    }

    // store
#pragma unroll
    for (int mb = 0; mb < MW; mb++) {
        int z0 = zbase + moff + mb * 16 + (lane >> 2);
#pragma unroll
        for (int j = 0; j < NBW; j++) {
            int n = (nb0 + j) * 8 + 2 * (lane & 3);
            float* aa = &acc[(mb * NBW + j) * 4];
            if (D == 1) {
                if (z0 < Z)
                    *(float2*)&out[(size_t)z0 * 480 + xoff + n] =
                        make_float2(alpha * aa[0], alpha * aa[1]);
                if (z0 + 8 < Z)
                    *(float2*)&out[(size_t)(z0 + 8) * 480 + xoff + n] =
                        make_float2(alpha * aa[2], alpha * aa[3]);
            } else {
                if (z0 < Z) {
                    out[(size_t)z0 * 480 + xoff + n * D + kc]       = alpha * aa[0];
                    out[(size_t)z0 * 480 + xoff + (n + 1) * D + kc] = alpha * aa[1];
                }
                if (z0 + 8 < Z) {
                    out[(size_t)(z0 + 8) * 480 + xoff + n * D + kc]       = alpha * aa[2];
                    out[(size_t)(z0 + 8) * 480 + xoff + (n + 1) * D + kc] = alpha * aa[3];
                }
            }
        }
    }
}

extern "C" void kernel_launch(void* const* d_in, const int* in_sizes, int n_in,
                              void* d_out, int out_size)
{
    const float* x   = (const float*)d_in[0];
    const float* opr = (const float*)d_in[1];
    const float* w0  = (const float*)d_in[2];
    const float* w1  = (const float*)d_in[3];
    const float* w2  = (const float*)d_in[4];
    float* out = (float*)d_out;

    const int Z  = in_sizes[1] / 16;
    const int GZ = (Z + 127) / 128;

    const float a0 = 0.022097086912079608f;  // 1/sqrt(128*16)
    const float a1 = 0.03125f;               // 1/sqrt(64*16)
    const float a2 = 0.044194173824159216f;  // 1/sqrt(32*16)

    void *p0, *p1, *p2;
    cudaGetSymbolAddress(&p0, BIMG0);
    cudaGetSymbolAddress(&p1, BIMG1);
    cudaGetSymbolAddress(&p2, BIMG2);

    prepB<128, 128><<<256, 256>>>(w0, (uint2*)p0);
    prepB< 64,  64><<< 64, 256>>>(w1, (uint2*)p1);
    prepB< 32,  32><<< 16, 256>>>(w2, (uint2*)p2);

    // path0: U=128, N=128; CTA n-tile 64 (grid.z=2); warps 4x2, tile m32xn32, VC=2
    {
        constexpr int SM = 2 * 128 * (128 + 8) * 2 + 128 * 17 * 4;  // 78336
        cudaFuncSetAttribute(fctp_hmma<128, 128, 64, 1, 4, 2, 2, 4, 2>,
                             cudaFuncAttributeMaxDynamicSharedMemorySize, SM);
        dim3 grid(GZ, 1, 2);
        fctp_hmma<128, 128, 64, 1, 4, 2, 2, 4, 2><<<grid, 256, SM>>>(
            x, opr, (const uint2*)p0, out, Z, 0, a0);
    }
    // path1: U=64, N=64; CTA n-tile 64; warps 4x2, m32xn32, VC=2
    {
        constexpr int SM = 2 * 128 * (64 + 8) * 2 + 128 * 17 * 4;   // 45568
        cudaFuncSetAttribute(fctp_hmma<64, 64, 64, 3, 4, 2, 2, 4, 2>,
                             cudaFuncAttributeMaxDynamicSharedMemorySize, SM);
        dim3 grid(GZ, 3, 1);
        fctp_hmma<64, 64, 64, 3, 4, 2, 2, 4, 2><<<grid, 256, SM>>>(
            x, opr, (const uint2*)p1, out, Z, 128, a1);
    }
    // path2: U=32, N=32; CTA n-tile 32; warps 4x2, m32xn16, VC=2
    {
        constexpr int SM = 2 * 128 * (32 + 8) * 2 + 128 * 17 * 4;   // 29184
        cudaFuncSetAttribute(fctp_hmma<32, 32, 32, 5, 4, 2, 2, 2, 2>,
                             cudaFuncAttributeMaxDynamicSharedMemorySize, SM);
        dim3 grid(GZ, 5, 1);
        fctp_hmma<32, 32, 32, 5, 4, 2, 2, 2, 2><<<grid, 256, SM>>>(
            x, opr, (const uint2*)p2, out, Z, 320, a2);
    }
}

// round 6
// speedup vs baseline: 1.2432x; 1.2432x over previous
#include <cuda_runtime.h>
#include <cuda_bf16.h>
#include <cstdint>

// SelfConnectionIntro via baseline-PTX HMMA (mma.sync m16n8k16 bf16):
// out_l[z,w,k] = alpha * sum_v opr[z,v] * (x_l[:,:,k] @ W_l[:,v,:])[z,w]
// Split-bf16, 3 terms: AhBh + AhBl + AlBh.
// R6: __launch_bounds__(256,2) (<=128 regs, 2 CTAs/SM); Ah shared across the
// two B terms (2 A-passes/v instead of 3); B hi+lo packed per lane as uint4
// (one LDG.128 feeds 2 MMAs); linear B image layout -> induction-variable
// addressing instead of 24 hoisted unique addresses.

__device__ __forceinline__ uint32_t smem_u32(const void* p) {
    uint32_t a;
    asm("{ .reg .u64 t; cvta.to.shared.u64 t, %1; cvt.u32.u64 %0, t; }" : "=r"(a) : "l"(p));
    return a;
}
__device__ __forceinline__ void ldmat_x4(uint32_t r[4], uint32_t a) {
    asm volatile("ldmatrix.sync.aligned.m8n8.x4.shared.b16 {%0,%1,%2,%3}, [%4];"
                 : "=r"(r[0]), "=r"(r[1]), "=r"(r[2]), "=r"(r[3]) : "r"(a));
}
__device__ __forceinline__ void mma16816(float d[4], const uint32_t a[4],
                                         uint32_t b0, uint32_t b1) {
    asm volatile("mma.sync.aligned.m16n8k16.row.col.f32.bf16.bf16.f32 "
                 "{%0,%1,%2,%3},{%4,%5,%6,%7},{%8,%9},{%0,%1,%2,%3};"
                 : "+f"(d[0]), "+f"(d[1]), "+f"(d[2]), "+f"(d[3])
                 : "r"(a[0]), "r"(a[1]), "r"(a[2]), "r"(a[3]), "r"(b0), "r"(b1));
}

// B images: [v(16)][ks][nb][lane(32)] of uint4 = {bh_r0, bh_r1, bl_r0, bl_r1}.
__device__ uint4 BIMG0[16 * 8 * 16 * 32];  // path0 U=128 N=128 (1 MB)
__device__ uint4 BIMG1[16 * 4 *  8 * 32];  // path1 U=64  N=64
__device__ uint4 BIMG2[16 * 2 *  4 * 32];  // path2 U=32  N=32

// W layout [U][16][NTOT]. HMMA B frag (k16 x n8): lane t, reg r, half hh:
//   u = ks*16 + 2*(t&3) + hh + r*8 ; n = nb*8 + t/4 ; value = W[u][v][n].
template<int U, int NTOT>
__global__ void prepB(const float* __restrict__ W, uint4* __restrict__ dst) {
    constexpr int KS = U / 16, NBT = NTOT / 8;
    const int total = 16 * KS * NBT * 32;
    for (int i = blockIdx.x * blockDim.x + threadIdx.x; i < total;
         i += gridDim.x * blockDim.x) {
        int lane = i & 31, r1 = i >> 5;
        int nb = r1 % NBT; r1 /= NBT;
        int ks = r1 % KS;  r1 /= KS;
        int v = r1;
        int n = nb * 8 + (lane >> 2);
        uint32_t wh[2], wl[2];
#pragma unroll
        for (int r = 0; r < 2; r++) {
            uint32_t whw = 0, wlw = 0;
#pragma unroll
            for (int hh = 0; hh < 2; hh++) {
                int u = ks * 16 + 2 * (lane & 3) + hh + r * 8;
                float f = W[((size_t)u * 16 + v) * NTOT + n];
                __nv_bfloat16 bh = __float2bfloat16(f);
                __nv_bfloat16 bl = __float2bfloat16(f - __bfloat162float(bh));
                whw |= (uint32_t)(*(uint16_t*)&bh) << (hh * 16);
                wlw |= (uint32_t)(*(uint16_t*)&bl) << (hh * 16);
            }
            wh[r] = whw; wl[r] = wlw;
        }
        dst[i] = make_uint4(wh[0], wh[1], wl[0], wl[1]);
    }
}

// Main kernel. CTA = 128-node tile x NT output channels, one k-component.
// Warps WM x WN, warp tile (MW*16) x (NBW*8). Per v: pass0 = Ah x (Bh,Bl),
// pass1 = Al x Bh; all into one d; epilogue acc += opr[z,v]*d.
template<int U, int NTOT, int NT, int D, int WM, int WN, int MW, int NBW>
__global__ __launch_bounds__(WM * WN * 32, 2)
void fctp_hmma(const float* __restrict__ x, const float* __restrict__ opr,
               const uint4* __restrict__ Bimg, float* __restrict__ out,
               int Z, int xoff, float alpha)
{
    constexpr int KS = U / 16, NBT = NTOT / 8, RS = U + 8;
    constexpr int NTH = WM * WN * 32;
    constexpr int XB = 128 * RS * 2;
    constexpr int AR = MW * NBW * 4;
    constexpr int STEPS = 2 * KS;                      // pass0: ks 0..KS-1, pass1: same

    extern __shared__ char smraw[];
    __nv_bfloat16* xh = (__nv_bfloat16*)smraw;
    __nv_bfloat16* xl = (__nv_bfloat16*)(smraw + XB);
    float* ops = (float*)(smraw + 2 * XB);             // [128][17]

    const int tid = threadIdx.x, lane = tid & 31, wid = tid >> 5;
    const int wm = wid % WM, wn = wid / WM;
    const int moff = wm * MW * 16;
    const int nb0 = blockIdx.z * (NT / 8) + wn * NBW;  // global n8-block
    const int kc = blockIdx.y;
    const int zbase = blockIdx.x * 128;

    // Stage x (split hi/lo bf16) and opr.
    for (int e = tid; e < 128 * U; e += NTH) {
        int zl = e / U, u = e % U;
        int z = zbase + zl;
        float v = (z < Z) ? x[(size_t)z * 480 + xoff + u * D + kc] : 0.0f;
        __nv_bfloat16 h = __float2bfloat16(v);
        xh[zl * RS + u] = h;
        xl[zl * RS + u] = __float2bfloat16(v - __bfloat162float(h));
    }
    for (int e = tid; e < 128 * 16; e += NTH) {
        int zl = e >> 4, v = e & 15;
        int z = zbase + zl;
        ops[zl * 17 + v] = (z < Z) ? opr[(size_t)z * 16 + v] : 0.0f;
    }
    __syncthreads();

    const uint32_t xhB = smem_u32(xh), xlB = smem_u32(xl);
    const uint32_t aLane = (uint32_t)(moff + (lane & 15)) * (RS * 2) + ((lane >> 4) << 4);
    const uint4* pB = Bimg + (size_t)nb0 * 32 + lane;  // + (v*KS+ks)*NBT*32 + j*32

    float acc[AR];
#pragma unroll
    for (int i = 0; i < AR; i++) acc[i] = 0.0f;

    uint32_t A[2][MW][4];
    uint4    Q[2][NBW];

    auto pfA = [&](int buf, int pass, int ks) {
        uint32_t base = (pass ? xlB : xhB) + aLane + ks * 32;
#pragma unroll
        for (int mb = 0; mb < MW; mb++) ldmat_x4(A[buf][mb], base + mb * 16 * RS * 2);
    };
    auto pfB = [&](int buf, int v, int ks) {
        const uint4* p = pB + (size_t)(v * KS + ks) * (NBT * 32);
#pragma unroll
        for (int j = 0; j < NBW; j++) Q[buf][j] = p[j * 32];
    };

    pfA(0, 0, 0);
    pfB(0, 0, 0);

    for (int v = 0; v < 16; v++) {
        float d[AR];
#pragma unroll
        for (int i = 0; i < AR; i++) d[i] = 0.0f;

#pragma unroll
        for (int s = 0; s < STEPS; s++) {
            constexpr int dummy = 0; (void)dummy;
            const int pass = s / KS, ks = s % KS;
            const int cur = s & 1, nxt = cur ^ 1;
            const int ns = s + 1;
            if (ns < STEPS) {
                pfA(nxt, ns / KS, ns % KS);
                pfB(nxt, v, ns % KS);          // pass1 re-reads same ks seq (L1 hit)
            } else if (v < 15) {
                pfA(nxt, 0, 0);
                pfB(nxt, v + 1, 0);
            }
            if (pass == 0) {
#pragma unroll
                for (int mb = 0; mb < MW; mb++)
#pragma unroll
                    for (int j = 0; j < NBW; j++) {
                        mma16816(&d[(mb * NBW + j) * 4], A[cur][mb], Q[cur][j].x, Q[cur][j].y);
                        mma16816(&d[(mb * NBW + j) * 4], A[cur][mb], Q[cur][j].z, Q[cur][j].w);
                    }
            } else {
#pragma unroll
                for (int mb = 0; mb < MW; mb++)
#pragma unroll
                    for (int j = 0; j < NBW; j++)
                        mma16816(&d[(mb * NBW + j) * 4], A[cur][mb], Q[cur][j].x, Q[cur][j].y);
            }
        }

        // epilogue: acc += opr[z,v] * d
#pragma unroll
        for (int mb = 0; mb < MW; mb++) {
            float o0 = ops[(moff + mb * 16 + (lane >> 2)) * 17 + v];
            float o1 = ops[(moff + mb * 16 + (lane >> 2) + 8) * 17 + v];
#pragma unroll
            for (int j = 0; j < NBW; j++) {
                float* dd = &d[(mb * NBW + j) * 4];
                float* aa = &acc[(mb * NBW + j) * 4];
                aa[0] = fmaf(o0, dd[0], aa[0]);
                aa[1] = fmaf(o0, dd[1], aa[1]);
                aa[2] = fmaf(o1, dd[2], aa[2]);
                aa[3] = fmaf(o1, dd[3], aa[3]);
            }
        }
    }

    // store
#pragma unroll
    for (int mb = 0; mb < MW; mb++) {
        int z0 = zbase + moff + mb * 16 + (lane >> 2);
#pragma unroll
        for (int j = 0; j < NBW; j++) {
            int n = (nb0 + j) * 8 + 2 * (lane & 3);
            float* aa = &acc[(mb * NBW + j) * 4];
            if (D == 1) {
                if (z0 < Z)
                    *(float2*)&out[(size_t)z0 * 480 + xoff + n] =
                        make_float2(alpha * aa[0], alpha * aa[1]);
                if (z0 + 8 < Z)
                    *(float2*)&out[(size_t)(z0 + 8) * 480 + xoff + n] =
                        make_float2(alpha * aa[2], alpha * aa[3]);
            } else {
                if (z0 < Z) {
                    out[(size_t)z0 * 480 + xoff + n * D + kc]       = alpha * aa[0];
                    out[(size_t)z0 * 480 + xoff + (n + 1) * D + kc] = alpha * aa[1];
                }
                if (z0 + 8 < Z) {
                    out[(size_t)(z0 + 8) * 480 + xoff + n * D + kc]       = alpha * aa[2];
                    out[(size_t)(z0 + 8) * 480 + xoff + (n + 1) * D + kc] = alpha * aa[3];
                }
            }
        }
    }
}

extern "C" void kernel_launch(void* const* d_in, const int* in_sizes, int n_in,
                              void* d_out, int out_size)
{
    const float* x   = (const float*)d_in[0];
    const float* opr = (const float*)d_in[1];
    const float* w0  = (const float*)d_in[2];
    const float* w1  = (const float*)d_in[3];
    const float* w2  = (const float*)d_in[4];
    float* out = (float*)d_out;

    const int Z  = in_sizes[1] / 16;
    const int GZ = (Z + 127) / 128;

    const float a0 = 0.022097086912079608f;  // 1/sqrt(128*16)
    const float a1 = 0.03125f;               // 1/sqrt(64*16)
    const float a2 = 0.044194173824159216f;  // 1/sqrt(32*16)

    void *p0, *p1, *p2;
    cudaGetSymbolAddress(&p0, BIMG0);
    cudaGetSymbolAddress(&p1, BIMG1);
    cudaGetSymbolAddress(&p2, BIMG2);

    prepB<128, 128><<<128, 256>>>(w0, (uint4*)p0);
    prepB< 64,  64><<< 32, 256>>>(w1, (uint4*)p1);
    prepB< 32,  32><<<  8, 256>>>(w2, (uint4*)p2);

    // path0: U=128, N=128; CTA 128x64 (grid.z=2); warps 4x2, warp m32xn32
    {
        constexpr int SM = 2 * 128 * (128 + 8) * 2 + 128 * 17 * 4;  // 78336
        cudaFuncSetAttribute(fctp_hmma<128, 128, 64, 1, 4, 2, 2, 4>,
                             cudaFuncAttributeMaxDynamicSharedMemorySize, SM);
        dim3 grid(GZ, 1, 2);
        fctp_hmma<128, 128, 64, 1, 4, 2, 2, 4><<<grid, 256, SM>>>(
            x, opr, (const uint4*)p0, out, Z, 0, a0);
    }
    // path1: U=64, N=64; CTA 128x64; warps 4x2, m32xn32
    {
        constexpr int SM = 2 * 128 * (64 + 8) * 2 + 128 * 17 * 4;   // 45568
        cudaFuncSetAttribute(fctp_hmma<64, 64, 64, 3, 4, 2, 2, 4>,
                             cudaFuncAttributeMaxDynamicSharedMemorySize, SM);
        dim3 grid(GZ, 3, 1);
        fctp_hmma<64, 64, 64, 3, 4, 2, 2, 4><<<grid, 256, SM>>>(
            x, opr, (const uint4*)p1, out, Z, 128, a1);
    }
    // path2: U=32, N=32; CTA 128x32; warps 4x2, m32xn16
    {
        constexpr int SM = 2 * 128 * (32 + 8) * 2 + 128 * 17 * 4;   // 29184
        cudaFuncSetAttribute(fctp_hmma<32, 32, 32, 5, 4, 2, 2, 2>,
                             cudaFuncAttributeMaxDynamicSharedMemorySize, SM);
        dim3 grid(GZ, 5, 1);
        fctp_hmma<32, 32, 32, 5, 4, 2, 2, 2><<<grid, 256, SM>>>(
            x, opr, (const uint4*)p2, out, Z, 320, a2);
    }
}